// round 14
// baseline (speedup 1.0000x reference)
#include <cuda_runtime.h>
#include <cuda_fp16.h>
#include <cstdint>

#define NP 50000
#define NPPAD 50048
#define NTOP 256
#define BATCH 1024
#define HALF_X 6400000
#define HALF_I 131072
#define KLB 25000
#define NTILES 391
#define NG 18

// dynamic smem (byte offsets)
#define SMO_A   0         // 4 chunks x {Ah,Al} x 16KB = 128KB
#define SMO_B   131072    // 2 stages x Bh 16KB = 32KB
#define SMO_RED 163840    // 128 x 4 float = 2KB
#define SMT_TOT 165888

__device__ __align__(256) __half g_Bh[NPPAD * NTOP];   // points: fp16 hi only
__device__ __align__(256) __half g_Ah[BATCH * NTOP];   // batch: hi
__device__ __align__(256) __half g_Al[BATCH * NTOP];   // batch: lo (a - hi)
__device__ float2 g_svrv[NPPAD];
__device__ float g_su[BATCH], g_ru[BATCH];
__device__ float g_partial[BATCH * NTILES];
__device__ float g_kldb[BATCH], g_rp[KLB];

// ---------- PTX helpers (plain sm_100-legal) ----------
__device__ __forceinline__ uint32_t smem_u32(const void* p) {
  uint32_t a;
  asm("{ .reg .u64 t; cvta.to.shared.u64 t, %1; cvt.u32.u64 %0, t; }" : "=r"(a) : "l"(p));
  return a;
}
#define SWZ128(o) ((o) ^ (((o) >> 3) & 0x70))
__device__ __forceinline__ void cpa16(uint32_t d, const void* s) {
  asm volatile("cp.async.cg.shared.global [%0], [%1], 16;" :: "r"(d), "l"(s));
}
#define CPCOMMIT() asm volatile("cp.async.commit_group;" ::: "memory")
#define CPWAIT0()  asm volatile("cp.async.wait_group 0;" ::: "memory")

#define LDSM4(r, addr) \
  asm volatile("ldmatrix.sync.aligned.m8n8.x4.shared.b16 {%0,%1,%2,%3}, [%4];" \
    : "=r"((r)[0]), "=r"((r)[1]), "=r"((r)[2]), "=r"((r)[3]) : "r"(addr))

#define MMA16816(d, a, b0r, b1r) \
  asm volatile("mma.sync.aligned.m16n8k16.row.col.f32.f16.f16.f32 " \
    "{%0,%1,%2,%3}, {%4,%5,%6,%7}, {%8,%9}, {%0,%1,%2,%3};" \
    : "+f"((d)[0]), "+f"((d)[1]), "+f"((d)[2]), "+f"((d)[3]) \
    : "r"((a)[0]), "r"((a)[1]), "r"((a)[2]), "r"((a)[3]), "r"(b0r), "r"(b1r))

// ---------- Threefry-2x32 (exact JAX) ----------
__host__ __device__ __forceinline__ void tf2x32(unsigned k0, unsigned k1,
                                                unsigned c0, unsigned c1,
                                                unsigned& o0, unsigned& o1) {
  unsigned ks2 = k0 ^ k1 ^ 0x1BD11BDAu;
  unsigned x0 = c0 + k0, x1 = c1 + k1;
#define TF_R(d) { x0 += x1; x1 = (x1 << (d)) | (x1 >> (32 - (d))); x1 ^= x0; }
  TF_R(13) TF_R(15) TF_R(26) TF_R(6)   x0 += k1;  x1 += ks2 + 1u;
  TF_R(17) TF_R(29) TF_R(16) TF_R(24)  x0 += ks2; x1 += k0 + 2u;
  TF_R(13) TF_R(15) TF_R(26) TF_R(6)   x0 += k0;  x1 += k1 + 3u;
  TF_R(17) TF_R(29) TF_R(16) TF_R(24)  x0 += k1;  x1 += ks2 + 4u;
  TF_R(13) TF_R(15) TF_R(26) TF_R(6)   x0 += ks2; x1 += k0 + 5u;
#undef TF_R
  o0 = x0; o1 = x1;
}
__device__ __forceinline__ float bits_to_normal(unsigned bits) {
  float f = __uint_as_float((bits >> 9) | 0x3f800000u) - 1.0f;
  float lo = __uint_as_float(0xBF7FFFFFu);
  return 1.41421356237f * erfinvf(fmaxf(lo, fmaf(f, 2.0f, lo)));
}
__device__ __forceinline__ float wred(float v) {
#pragma unroll
  for (int o = 16; o > 0; o >>= 1) v += __shfl_xor_sync(0xffffffffu, v, o);
  return v;
}

// ---------- warp-per-row fused sample + double transform ----------
__device__ __forceinline__ void row_transform(const float* x, float sx, int row,
                                              int lane, int is_batch) {
  float s1 = 1.f + sqrtf(1.f + sx);
  float sy = sx / (s1 * s1);
  float s2 = 1.f + sqrtf(1.f + sy);
  float scale = 1.f / (s1 * s2);
  if (is_batch) {
#pragma unroll
    for (int k = 0; k < 8; k++) {
      float p = x[k] * scale;
      __half hi = __float2half_rn(p);
      int col = k * 32 + lane;
      g_Ah[row * NTOP + col] = hi;
      g_Al[row * NTOP + col] = __float2half_rn(p - __half2float(hi));
    }
  } else {
#pragma unroll
    for (int k = 0; k < 8; k++) {
      int col = k * 32 + lane;
      g_Bh[row * NTOP + col] = __float2half_rn(x[k] * scale);
    }
  }
  if (lane == 0) {
    float sp = sy / (s2 * s2);
    float sv = fminf(fmaxf(sp, 0.f), 1.f - 1e-5f);
    float rv = 1.f / (1.f - sv);
    if (is_batch) { g_su[row] = sv; g_ru[row] = rv; }
    else g_svrv[row] = make_float2(sv, rv);
  }
}

__global__ __launch_bounds__(256) void kA(const float* __restrict__ mu,
                                          const float* __restrict__ lv,
                                          unsigned kx0, unsigned kx1) {
  int w = threadIdx.x >> 5, lane = threadIdx.x & 31;
  int r = blockIdx.x * 8 + w;
  int r2 = r + 25000;
  float x1[8], x2[8];
  float sx1 = 0.f, sx2 = 0.f, kl = 0.f;
#pragma unroll
  for (int k = 0; k < 8; k++) {
    int g = r * NTOP + k * 32 + lane;
    unsigned b0, b1;
    tf2x32(kx0, kx1, (unsigned)g, (unsigned)(g + HALF_X), b0, b1);
    float m1 = mu[g], l1 = lv[g];
    float sd1 = expf(0.5f * l1);
    x1[k] = fmaf(bits_to_normal(b0), sd1, m1);
    kl += 1.0f + l1 - m1 * m1 - sd1 * sd1;
    int g2 = g + HALF_X;
    float m2 = mu[g2], l2 = lv[g2];
    float sd2 = expf(0.5f * l2);
    x2[k] = fmaf(bits_to_normal(b1), sd2, m2);
    kl += 1.0f + l2 - m2 * m2 - sd2 * sd2;
    sx1 += x1[k] * x1[k];
    sx2 += x2[k] * x2[k];
  }
  sx1 = wred(sx1); sx2 = wred(sx2); kl = wred(kl);
  row_transform(x1, sx1, r,  lane, 0);
  row_transform(x2, sx2, r2, lane, 0);
  if (lane == 0) g_rp[r] = kl;
}

__global__ __launch_bounds__(256) void kB(const float* __restrict__ mu,
                                          const float* __restrict__ lv,
                                          const int* __restrict__ iidx,
                                          unsigned ki0, unsigned ki1) {
  int w = threadIdx.x >> 5, lane = threadIdx.x & 31;
  int r = blockIdx.x * 8 + w;
  int r2 = r + 512;
  int i1 = iidx[r], i2 = iidx[r2];
  float x1[8], x2[8];
  float sx1 = 0.f, sx2 = 0.f;
#pragma unroll
  for (int k = 0; k < 8; k++) {
    int col = k * 32 + lane;
    int f = r * NTOP + col;
    unsigned b0, b1;
    tf2x32(ki0, ki1, (unsigned)f, (unsigned)(f + HALF_I), b0, b1);
    int a0 = i1 * NTOP + col, a1 = i2 * NTOP + col;
    x1[k] = fmaf(bits_to_normal(b0), expf(0.5f * lv[a0]), mu[a0]);
    x2[k] = fmaf(bits_to_normal(b1), expf(0.5f * lv[a1]), mu[a1]);
    sx1 += x1[k] * x1[k];
    sx2 += x2[k] * x2[k];
  }
  sx1 = wred(sx1); sx2 = wred(sx2);
  row_transform(x1, sx1, r,  lane, 1);
  row_transform(x2, sx2, r2, lane, 1);
}

// ---------- K5: persistent mma.sync fp16x2 GEMM, 16 warps, fused epilogue ----------
// dot = (ah + al) . bh ; only error is a.bl (~2.6e-6 absolute).
__global__ __launch_bounds__(512, 1) void k5_gemm() {
  extern __shared__ char smc[];
  uint32_t sb = smem_u32(smc);
  int t = threadIdx.x, w = t >> 5, lane = t & 31;
  int wm = w & 3, wn = w >> 2;
  int grp = blockIdx.x, b0 = blockIdx.y * 128;
  int ntiles = (NTILES - grp + NG - 1) / NG;

  // per-thread cp.async offsets: 512 threads cover a 16KB tile in 2 rounds
  int tr = t >> 3, li = t & 7;     // tr 0..63, li 0..7
  uint32_t dstoff[2];
#pragma unroll
  for (int q = 0; q < 2; q++)
    dstoff[q] = SWZ128((uint32_t)((q * 64 + tr) * 128 + li * 16));
  uint32_t soff = (uint32_t)(tr * 512 + li * 16);
  const char* bhp = (const char*)g_Bh;

  float sub[4], rub2[4];
#pragma unroll
  for (int i = 0; i < 4; i++) {
    int row = b0 + wm * 32 + (i >> 1) * 16 + (lane >> 2) + (i & 1) * 8;
    sub[i] = g_su[row];
    rub2[i] = 2.f * g_ru[row];
  }

  // startup: resident A (4 chunks x hi/lo), B chunk0 of first tile
#pragma unroll
  for (int c = 0; c < 4; c++) {
#pragma unroll
    for (int q = 0; q < 2; q++) {
      uint32_t so = (uint32_t)(b0 * 512 + c * 128 + q * 32768) + soff;
      cpa16(sb + SMO_A + c * 32768 +         dstoff[q], (const char*)g_Ah + so);
      cpa16(sb + SMO_A + c * 32768 + 16384 + dstoff[q], (const char*)g_Al + so);
    }
  }
  {
    uint32_t so = (uint32_t)(grp * 128 * 512) + soff;
#pragma unroll
    for (int q = 0; q < 2; q++)
      cpa16(sb + SMO_B + dstoff[q], bhp + so + q * 32768);
  }
  CPCOMMIT();

  // ldmatrix address components (hoisted)
  uint32_t a_base[2], a_xor[2];
#pragma unroll
  for (int mt = 0; mt < 2; mt++) {
    int r = wm * 32 + mt * 16 + (lane & 15);
    a_base[mt] = (uint32_t)(r * 128);
    a_xor[mt] = (uint32_t)(r & 7);
  }
  uint32_t b_base[2], b_xor[2];
#pragma unroll
  for (int q = 0; q < 2; q++) {
    int r = wn * 32 + q * 16 + (lane & 15);
    b_base[q] = (uint32_t)(r * 128);
    b_xor[q] = (uint32_t)(r & 7);
  }
  uint32_t ly = (uint32_t)(lane >> 4);

  unsigned cc = 0;
  for (int ti = 0; ti < ntiles; ti++) {
    int nt = grp + ti * NG;
    float acc[2][4][4];
#pragma unroll
    for (int a = 0; a < 2; a++)
#pragma unroll
      for (int b = 0; b < 4; b++)
#pragma unroll
        for (int e = 0; e < 4; e++) acc[a][b][e] = 0.f;

    for (int c = 0; c < 4; c++, cc++) {
      CPWAIT0();
      __syncthreads();
      bool has_next = (c < 3) || (ti < ntiles - 1);
      if (has_next) {
        int nc = (c + 1) & 3;
        int nrt = (c == 3) ? nt + NG : nt;
        uint32_t bs = sb + SMO_B + ((cc + 1) & 1) * 16384;
        uint32_t so = (uint32_t)(nrt * 128 * 512 + nc * 128) + soff;
#pragma unroll
        for (int q = 0; q < 2; q++)
          cpa16(bs + dstoff[q], bhp + so + q * 32768);
        CPCOMMIT();
      }

      uint32_t ab = sb + SMO_A + c * 32768;
      uint32_t bb = sb + SMO_B + (cc & 1) * 16384;
#pragma unroll
      for (int ks = 0; ks < 4; ks++) {
        uint32_t kg = (uint32_t)(ks * 2) + ly;
        uint32_t aH[2][4], aL[2][4], bF[2][4];
#pragma unroll
        for (int mt = 0; mt < 2; mt++) {
          uint32_t ad = ab + a_base[mt] + ((kg ^ a_xor[mt]) << 4);
          LDSM4(aH[mt], ad);
          LDSM4(aL[mt], ad + 16384);
        }
#pragma unroll
        for (int q = 0; q < 2; q++) {
          uint32_t bd = bb + b_base[q] + ((kg ^ b_xor[q]) << 4);
          LDSM4(bF[q], bd);
        }
        // pass 1: ah * bh
#pragma unroll
        for (int q = 0; q < 2; q++)
#pragma unroll
          for (int mt = 0; mt < 2; mt++) {
            MMA16816(acc[mt][2 * q],     aH[mt], bF[q][0], bF[q][2]);
            MMA16816(acc[mt][2 * q + 1], aH[mt], bF[q][1], bF[q][3]);
          }
        // pass 2: al * bh
#pragma unroll
        for (int q = 0; q < 2; q++)
#pragma unroll
          for (int mt = 0; mt < 2; mt++) {
            MMA16816(acc[mt][2 * q],     aL[mt], bF[q][0], bF[q][2]);
            MMA16816(acc[mt][2 * q + 1], aL[mt], bF[q][1], bF[q][3]);
          }
      }
    }

    // epilogue: e = x + sqrt(x^2-1) from register accumulators
    int nbase = nt * 128;
    int limit = NP - nbase;
    float rs[4] = {0.f, 0.f, 0.f, 0.f};
#pragma unroll
    for (int q = 0; q < 4; q++)
#pragma unroll
      for (int e2 = 0; e2 < 2; e2++) {
        int nl = wn * 32 + q * 8 + 2 * (lane & 3) + e2;
        if (nl < limit) {
          float2 sr = __ldg(&g_svrv[nbase + nl]);
#pragma unroll
          for (int mt = 0; mt < 2; mt++)
#pragma unroll
            for (int eh = 0; eh < 2; eh++) {
              int ri = mt * 2 + eh;
              float qd = fmaxf(fmaf(acc[mt][q][eh * 2 + e2], -2.f, sub[ri] + sr.x), 0.f);
              float xx = fmaxf(fmaf(qd, rub2[ri] * sr.y, 1.f), 1.0f + 1e-7f);
              float s;
              asm("sqrt.approx.f32 %0, %1;" : "=f"(s) : "f"(fmaf(xx, xx, -1.f)));
              rs[ri] += xx + s;
            }
        }
      }
    float* red = (float*)(smc + SMO_RED);
#pragma unroll
    for (int i = 0; i < 4; i++) {
      rs[i] += __shfl_xor_sync(0xffffffffu, rs[i], 1);
      rs[i] += __shfl_xor_sync(0xffffffffu, rs[i], 2);
      if ((lane & 3) == 0) {
        int row = wm * 32 + (i >> 1) * 16 + (lane >> 2) + (i & 1) * 8;
        red[row * 4 + wn] = rs[i];
      }
    }
    __syncthreads();
    if (t < 128)
      g_partial[(b0 + t) * NTILES + nt] =
          (red[t * 4] + red[t * 4 + 1]) + (red[t * 4 + 2] + red[t * 4 + 3]);
    __syncthreads();
  }
}

// ---------- tails (k7 fused into k6) ----------
__global__ __launch_bounds__(256) void k6_lse(const float* __restrict__ pij,
                                              const int* __restrict__ jidx) {
  int b = blockIdx.x, t = threadIdx.x;
  int jb = jidx[b];
  float av = __half2float(g_Ah[b * NTOP + t]) + __half2float(g_Al[b * NTOP + t]);
  float vv = __half2float(g_Bh[jb * NTOP + t]);
  float pr = av * vv;
  float s = 0.f;
  for (int q = t; q < NTILES; q += 256) s += g_partial[b * NTILES + q];
  __shared__ float sh[256], sh2[256];
  sh[t] = s; sh2[t] = pr; __syncthreads();
  for (int w = 128; w > 0; w >>= 1) {
    if (t < w) { sh[t] += sh[t + w]; sh2[t] += sh2[t + w]; }
    __syncthreads();
  }
  if (t == 0) {
    float2 sr = g_svrv[jb];
    float sq = fmaxf(g_su[b] + sr.x - 2.f * sh2[0], 0.f);
    float xx = fmaxf(fmaf(2.f * sq, g_ru[b] * sr.y, 1.f), 1.0f + 1e-7f);
    float dj = logf(xx + sqrtf(fmaf(xx, xx, -1.f)));
    float pb = pij[b];
    g_kldb[b] = pb * (logf(pb) - (dj - logf(sh[0])));
  }
}

__global__ __launch_bounds__(256) void k8_final(float* __restrict__ out) {
  int t = threadIdx.x;
  __shared__ double shd[256];
  double s1 = 0.0, s2 = 0.0;
  for (int b = t; b < BATCH; b += 256) s1 += (double)g_kldb[b];
  for (int q = t; q < KLB; q += 256) s2 += (double)g_rp[q];
  shd[t] = s1; __syncthreads();
  for (int w = 128; w > 0; w >>= 1) { if (t < w) shd[t] += shd[t + w]; __syncthreads(); }
  double kldsum = shd[0]; __syncthreads();
  shd[t] = s2; __syncthreads();
  for (int w = 128; w > 0; w >>= 1) { if (t < w) shd[t] += shd[t + w]; __syncthreads(); }
  if (t == 0)
    out[0] = (float)(kldsum + (-0.5 * shd[0]) * (1024.0 / (50000.0 * 50000.0)));
}

extern "C" void kernel_launch(void* const* d_in, const int* in_sizes, int n_in,
                              void* d_out, int out_size) {
  const float* pij = (const float*)d_in[0];
  const float* mu  = (const float*)d_in[1];
  const float* lv  = (const float*)d_in[2];
  const int*   ii  = (const int*)d_in[3];
  const int*   jj  = (const int*)d_in[4];
  float* out = (float*)d_out;

  unsigned A0, B0, A1, B1;
  tf2x32(0u, 42u, 0u, 2u, A0, B0);   // kx
  tf2x32(0u, 42u, 1u, 3u, A1, B1);   // ki

  cudaFuncSetAttribute(k5_gemm, cudaFuncAttributeMaxDynamicSharedMemorySize, SMT_TOT);

  kA<<<3125, 256>>>(mu, lv, A0, A1);
  kB<<<64, 256>>>(mu, lv, ii, B0, B1);
  k5_gemm<<<dim3(NG, 8), 512, SMT_TOT>>>();
  k6_lse<<<BATCH, 256>>>(pij, jj);
  k8_final<<<1, 256>>>(out);
}

// round 16
// speedup vs baseline: 1.3375x; 1.3375x over previous
#include <cuda_runtime.h>
#include <cuda_fp16.h>
#include <cstdint>

#define NP 50000
#define NPPAD 50048
#define NTOP 256
#define BATCH 1024
#define HALF_X 6400000
#define HALF_I 131072
#define KLB 25000
#define NTILES 391
#define NG 18

// dynamic smem (byte offsets)
#define SMO_A   0         // 4 chunks x Ah 16KB = 64KB
#define SMO_B   65536     // 2 stages x Bh 16KB = 32KB
#define SMO_RED 98304     // 128 x 4 float = 2KB
#define SMT_TOT 100352

__device__ __align__(256) __half g_Bh[NPPAD * NTOP];   // points: fp16
__device__ __align__(256) __half g_Ah[BATCH * NTOP];   // batch: fp16
__device__ float2 g_svrv[NPPAD];
__device__ float g_su[BATCH], g_ru[BATCH];
__device__ float g_partial[BATCH * NTILES];
__device__ float g_kldb[BATCH], g_rp[KLB];

// ---------- PTX helpers (plain sm_100-legal) ----------
__device__ __forceinline__ uint32_t smem_u32(const void* p) {
  uint32_t a;
  asm("{ .reg .u64 t; cvta.to.shared.u64 t, %1; cvt.u32.u64 %0, t; }" : "=r"(a) : "l"(p));
  return a;
}
#define SWZ128(o) ((o) ^ (((o) >> 3) & 0x70))
__device__ __forceinline__ void cpa16(uint32_t d, const void* s) {
  asm volatile("cp.async.cg.shared.global [%0], [%1], 16;" :: "r"(d), "l"(s));
}
#define CPCOMMIT() asm volatile("cp.async.commit_group;" ::: "memory")
#define CPWAIT0()  asm volatile("cp.async.wait_group 0;" ::: "memory")

#define LDSM4(r, addr) \
  asm volatile("ldmatrix.sync.aligned.m8n8.x4.shared.b16 {%0,%1,%2,%3}, [%4];" \
    : "=r"((r)[0]), "=r"((r)[1]), "=r"((r)[2]), "=r"((r)[3]) : "r"(addr))

#define MMA16816(d, a, b0r, b1r) \
  asm volatile("mma.sync.aligned.m16n8k16.row.col.f32.f16.f16.f32 " \
    "{%0,%1,%2,%3}, {%4,%5,%6,%7}, {%8,%9}, {%0,%1,%2,%3};" \
    : "+f"((d)[0]), "+f"((d)[1]), "+f"((d)[2]), "+f"((d)[3]) \
    : "r"((a)[0]), "r"((a)[1]), "r"((a)[2]), "r"((a)[3]), "r"(b0r), "r"(b1r))

// ---------- Threefry-2x32 (exact JAX) ----------
__host__ __device__ __forceinline__ void tf2x32(unsigned k0, unsigned k1,
                                                unsigned c0, unsigned c1,
                                                unsigned& o0, unsigned& o1) {
  unsigned ks2 = k0 ^ k1 ^ 0x1BD11BDAu;
  unsigned x0 = c0 + k0, x1 = c1 + k1;
#define TF_R(d) { x0 += x1; x1 = (x1 << (d)) | (x1 >> (32 - (d))); x1 ^= x0; }
  TF_R(13) TF_R(15) TF_R(26) TF_R(6)   x0 += k1;  x1 += ks2 + 1u;
  TF_R(17) TF_R(29) TF_R(16) TF_R(24)  x0 += ks2; x1 += k0 + 2u;
  TF_R(13) TF_R(15) TF_R(26) TF_R(6)   x0 += k0;  x1 += k1 + 3u;
  TF_R(17) TF_R(29) TF_R(16) TF_R(24)  x0 += k1;  x1 += ks2 + 4u;
  TF_R(13) TF_R(15) TF_R(26) TF_R(6)   x0 += ks2; x1 += k0 + 5u;
#undef TF_R
  o0 = x0; o1 = x1;
}
__device__ __forceinline__ float bits_to_normal(unsigned bits) {
  float f = __uint_as_float((bits >> 9) | 0x3f800000u) - 1.0f;
  float lo = __uint_as_float(0xBF7FFFFFu);
  return 1.41421356237f * erfinvf(fmaxf(lo, fmaf(f, 2.0f, lo)));
}
__device__ __forceinline__ float wred(float v) {
#pragma unroll
  for (int o = 16; o > 0; o >>= 1) v += __shfl_xor_sync(0xffffffffu, v, o);
  return v;
}

// ---------- warp-per-row fused sample + double transform ----------
__device__ __forceinline__ void row_transform(const float* x, float sx, int row,
                                              __half* dst, int lane, int is_batch) {
  float s1 = 1.f + sqrtf(1.f + sx);
  float sy = sx / (s1 * s1);
  float s2 = 1.f + sqrtf(1.f + sy);
  float scale = 1.f / (s1 * s2);
#pragma unroll
  for (int k = 0; k < 8; k++) {
    int col = k * 32 + lane;
    dst[row * NTOP + col] = __float2half_rn(x[k] * scale);
  }
  if (lane == 0) {
    float sp = sy / (s2 * s2);
    float sv = fminf(fmaxf(sp, 0.f), 1.f - 1e-5f);
    float rv = 1.f / (1.f - sv);
    if (is_batch) { g_su[row] = sv; g_ru[row] = rv; }
    else g_svrv[row] = make_float2(sv, rv);
  }
}

__global__ __launch_bounds__(256) void kA(const float* __restrict__ mu,
                                          const float* __restrict__ lv,
                                          unsigned kx0, unsigned kx1) {
  int w = threadIdx.x >> 5, lane = threadIdx.x & 31;
  int r = blockIdx.x * 8 + w;
  int r2 = r + 25000;
  float x1[8], x2[8];
  float sx1 = 0.f, sx2 = 0.f, kl = 0.f;
#pragma unroll
  for (int k = 0; k < 8; k++) {
    int g = r * NTOP + k * 32 + lane;
    unsigned b0, b1;
    tf2x32(kx0, kx1, (unsigned)g, (unsigned)(g + HALF_X), b0, b1);
    float m1 = mu[g], l1 = lv[g];
    float sd1 = expf(0.5f * l1);
    x1[k] = fmaf(bits_to_normal(b0), sd1, m1);
    kl += 1.0f + l1 - m1 * m1 - sd1 * sd1;
    int g2 = g + HALF_X;
    float m2 = mu[g2], l2 = lv[g2];
    float sd2 = expf(0.5f * l2);
    x2[k] = fmaf(bits_to_normal(b1), sd2, m2);
    kl += 1.0f + l2 - m2 * m2 - sd2 * sd2;
    sx1 += x1[k] * x1[k];
    sx2 += x2[k] * x2[k];
  }
  sx1 = wred(sx1); sx2 = wred(sx2); kl = wred(kl);
  row_transform(x1, sx1, r,  g_Bh, lane, 0);
  row_transform(x2, sx2, r2, g_Bh, lane, 0);
  if (lane == 0) g_rp[r] = kl;
}

__global__ __launch_bounds__(256) void kB(const float* __restrict__ mu,
                                          const float* __restrict__ lv,
                                          const int* __restrict__ iidx,
                                          unsigned ki0, unsigned ki1) {
  int w = threadIdx.x >> 5, lane = threadIdx.x & 31;
  int r = blockIdx.x * 8 + w;
  int r2 = r + 512;
  int i1 = iidx[r], i2 = iidx[r2];
  float x1[8], x2[8];
  float sx1 = 0.f, sx2 = 0.f;
#pragma unroll
  for (int k = 0; k < 8; k++) {
    int col = k * 32 + lane;
    int f = r * NTOP + col;
    unsigned b0, b1;
    tf2x32(ki0, ki1, (unsigned)f, (unsigned)(f + HALF_I), b0, b1);
    int a0 = i1 * NTOP + col, a1 = i2 * NTOP + col;
    x1[k] = fmaf(bits_to_normal(b0), expf(0.5f * lv[a0]), mu[a0]);
    x2[k] = fmaf(bits_to_normal(b1), expf(0.5f * lv[a1]), mu[a1]);
    sx1 += x1[k] * x1[k];
    sx2 += x2[k] * x2[k];
  }
  sx1 = wred(sx1); sx2 = wred(sx2);
  row_transform(x1, sx1, r,  g_Ah, lane, 1);
  row_transform(x2, sx2, r2, g_Ah, lane, 1);
}

// ---------- K5: persistent mma.sync fp16 single-pass GEMM, 16 warps ----------
__global__ __launch_bounds__(512, 1) void k5_gemm() {
  extern __shared__ char smc[];
  uint32_t sb = smem_u32(smc);
  int t = threadIdx.x, w = t >> 5, lane = t & 31;
  int wm = w & 3, wn = w >> 2;
  int grp = blockIdx.x, b0 = blockIdx.y * 128;
  int ntiles = (NTILES - grp + NG - 1) / NG;

  // per-thread cp.async offsets: 512 threads cover a 16KB tile in 2 rounds
  int tr = t >> 3, li = t & 7;
  uint32_t dstoff[2];
#pragma unroll
  for (int q = 0; q < 2; q++)
    dstoff[q] = SWZ128((uint32_t)((q * 64 + tr) * 128 + li * 16));
  uint32_t soff = (uint32_t)(tr * 512 + li * 16);
  const char* bhp = (const char*)g_Bh;

  float sub[4], rub2[4];
#pragma unroll
  for (int i = 0; i < 4; i++) {
    int row = b0 + wm * 32 + (i >> 1) * 16 + (lane >> 2) + (i & 1) * 8;
    sub[i] = g_su[row];
    rub2[i] = 2.f * g_ru[row];
  }

  // startup: resident A (4 chunks), B chunk0 of first tile
#pragma unroll
  for (int c = 0; c < 4; c++) {
#pragma unroll
    for (int q = 0; q < 2; q++) {
      uint32_t so = (uint32_t)(b0 * 512 + c * 128 + q * 32768) + soff;
      cpa16(sb + SMO_A + c * 16384 + dstoff[q], (const char*)g_Ah + so);
    }
  }
  {
    uint32_t so = (uint32_t)(grp * 128 * 512) + soff;
#pragma unroll
    for (int q = 0; q < 2; q++)
      cpa16(sb + SMO_B + dstoff[q], bhp + so + q * 32768);
  }
  CPCOMMIT();

  // ldmatrix address components (hoisted)
  uint32_t a_base[2], a_xor[2];
#pragma unroll
  for (int mt = 0; mt < 2; mt++) {
    int r = wm * 32 + mt * 16 + (lane & 15);
    a_base[mt] = (uint32_t)(r * 128);
    a_xor[mt] = (uint32_t)(r & 7);
  }
  uint32_t b_base[2], b_xor[2];
#pragma unroll
  for (int q = 0; q < 2; q++) {
    int r = wn * 32 + q * 16 + (lane & 15);
    b_base[q] = (uint32_t)(r * 128);
    b_xor[q] = (uint32_t)(r & 7);
  }
  uint32_t ly = (uint32_t)(lane >> 4);

  unsigned cc = 0;
  for (int ti = 0; ti < ntiles; ti++) {
    int nt = grp + ti * NG;
    float acc[2][4][4];
#pragma unroll
    for (int a = 0; a < 2; a++)
#pragma unroll
      for (int b = 0; b < 4; b++)
#pragma unroll
        for (int e = 0; e < 4; e++) acc[a][b][e] = 0.f;

    for (int c = 0; c < 4; c++, cc++) {
      CPWAIT0();
      __syncthreads();
      bool has_next = (c < 3) || (ti < ntiles - 1);
      if (has_next) {
        int nc = (c + 1) & 3;
        int nrt = (c == 3) ? nt + NG : nt;
        uint32_t bs = sb + SMO_B + ((cc + 1) & 1) * 16384;
        uint32_t so = (uint32_t)(nrt * 128 * 512 + nc * 128) + soff;
#pragma unroll
        for (int q = 0; q < 2; q++)
          cpa16(bs + dstoff[q], bhp + so + q * 32768);
        CPCOMMIT();
      }

      uint32_t ab = sb + SMO_A + c * 16384;
      uint32_t bb = sb + SMO_B + (cc & 1) * 16384;
#pragma unroll
      for (int ks = 0; ks < 4; ks++) {
        uint32_t kg = (uint32_t)(ks * 2) + ly;
        uint32_t aH[2][4], bF[2][4];
#pragma unroll
        for (int mt = 0; mt < 2; mt++) {
          uint32_t ad = ab + a_base[mt] + ((kg ^ a_xor[mt]) << 4);
          LDSM4(aH[mt], ad);
        }
#pragma unroll
        for (int q = 0; q < 2; q++) {
          uint32_t bd = bb + b_base[q] + ((kg ^ b_xor[q]) << 4);
          LDSM4(bF[q], bd);
        }
#pragma unroll
        for (int q = 0; q < 2; q++)
#pragma unroll
          for (int mt = 0; mt < 2; mt++) {
            MMA16816(acc[mt][2 * q],     aH[mt], bF[q][0], bF[q][2]);
            MMA16816(acc[mt][2 * q + 1], aH[mt], bF[q][1], bF[q][3]);
          }
      }
    }

    // epilogue: e = x + sqrt(x^2-1) from register accumulators
    int nbase = nt * 128;
    int limit = NP - nbase;
    float rs[4] = {0.f, 0.f, 0.f, 0.f};
#pragma unroll
    for (int q = 0; q < 4; q++)
#pragma unroll
      for (int e2 = 0; e2 < 2; e2++) {
        int nl = wn * 32 + q * 8 + 2 * (lane & 3) + e2;
        if (nl < limit) {
          float2 sr = __ldg(&g_svrv[nbase + nl]);
#pragma unroll
          for (int mt = 0; mt < 2; mt++)
#pragma unroll
            for (int eh = 0; eh < 2; eh++) {
              int ri = mt * 2 + eh;
              float qd = fmaxf(fmaf(acc[mt][q][eh * 2 + e2], -2.f, sub[ri] + sr.x), 0.f);
              float xx = fmaxf(fmaf(qd, rub2[ri] * sr.y, 1.f), 1.0f + 1e-7f);
              float s;
              asm("sqrt.approx.f32 %0, %1;" : "=f"(s) : "f"(fmaf(xx, xx, -1.f)));
              rs[ri] += xx + s;
            }
        }
      }
    float* red = (float*)(smc + SMO_RED);
#pragma unroll
    for (int i = 0; i < 4; i++) {
      rs[i] += __shfl_xor_sync(0xffffffffu, rs[i], 1);
      rs[i] += __shfl_xor_sync(0xffffffffu, rs[i], 2);
      if ((lane & 3) == 0) {
        int row = wm * 32 + (i >> 1) * 16 + (lane >> 2) + (i & 1) * 8;
        red[row * 4 + wn] = rs[i];
      }
    }
    __syncthreads();
    if (t < 128)
      g_partial[(b0 + t) * NTILES + nt] =
          (red[t * 4] + red[t * 4 + 1]) + (red[t * 4 + 2] + red[t * 4 + 3]);
    __syncthreads();
  }
}

// ---------- tails (k7 fused into k6) ----------
__global__ __launch_bounds__(256) void k6_lse(const float* __restrict__ pij,
                                              const int* __restrict__ jidx) {
  int b = blockIdx.x, t = threadIdx.x;
  int jb = jidx[b];
  float av = __half2float(g_Ah[b * NTOP + t]);
  float vv = __half2float(g_Bh[jb * NTOP + t]);
  float pr = av * vv;
  float s = 0.f;
  for (int q = t; q < NTILES; q += 256) s += g_partial[b * NTILES + q];
  __shared__ float sh[256], sh2[256];
  sh[t] = s; sh2[t] = pr; __syncthreads();
  for (int w = 128; w > 0; w >>= 1) {
    if (t < w) { sh[t] += sh[t + w]; sh2[t] += sh2[t + w]; }
    __syncthreads();
  }
  if (t == 0) {
    float2 sr = g_svrv[jb];
    float sq = fmaxf(g_su[b] + sr.x - 2.f * sh2[0], 0.f);
    float xx = fmaxf(fmaf(2.f * sq, g_ru[b] * sr.y, 1.f), 1.0f + 1e-7f);
    float dj = logf(xx + sqrtf(fmaf(xx, xx, -1.f)));
    float pb = pij[b];
    g_kldb[b] = pb * (logf(pb) - (dj - logf(sh[0])));
  }
}

__global__ __launch_bounds__(256) void k8_final(float* __restrict__ out) {
  int t = threadIdx.x;
  __shared__ double shd[256];
  double s1 = 0.0, s2 = 0.0;
  for (int b = t; b < BATCH; b += 256) s1 += (double)g_kldb[b];
  for (int q = t; q < KLB; q += 256) s2 += (double)g_rp[q];
  shd[t] = s1; __syncthreads();
  for (int w = 128; w > 0; w >>= 1) { if (t < w) shd[t] += shd[t + w]; __syncthreads(); }
  double kldsum = shd[0]; __syncthreads();
  shd[t] = s2; __syncthreads();
  for (int w = 128; w > 0; w >>= 1) { if (t < w) shd[t] += shd[t + w]; __syncthreads(); }
  if (t == 0)
    out[0] = (float)(kldsum + (-0.5 * shd[0]) * (1024.0 / (50000.0 * 50000.0)));
}

extern "C" void kernel_launch(void* const* d_in, const int* in_sizes, int n_in,
                              void* d_out, int out_size) {
  const float* pij = (const float*)d_in[0];
  const float* mu  = (const float*)d_in[1];
  const float* lv  = (const float*)d_in[2];
  const int*   ii  = (const int*)d_in[3];
  const int*   jj  = (const int*)d_in[4];
  float* out = (float*)d_out;

  unsigned A0, B0, A1, B1;
  tf2x32(0u, 42u, 0u, 2u, A0, B0);   // kx
  tf2x32(0u, 42u, 1u, 3u, A1, B1);   // ki

  cudaFuncSetAttribute(k5_gemm, cudaFuncAttributeMaxDynamicSharedMemorySize, SMT_TOT);

  kA<<<3125, 256>>>(mu, lv, A0, A1);
  kB<<<64, 256>>>(mu, lv, ii, B0, B1);
  k5_gemm<<<dim3(NG, 8), 512, SMT_TOT>>>();
  k6_lse<<<BATCH, 256>>>(pij, jj);
  k8_final<<<1, 256>>>(out);
}